// round 1
// baseline (speedup 1.0000x reference)
#include <cuda_runtime.h>
#include <math.h>

#define THREADS 256

constexpr int NT  = 64;    // tokens per window
constexpr int CD  = 96;    // channels
constexpr int NHEADS = 3;
constexpr int HD  = 32;
constexpr int HID = 192;
constexpr float LN_EPS = 1e-5f;

// smem layout (floats)
constexpr int A_STR = 97;
constexpr int Q_STR = 289;
constexpr int W_STR = 296;
constexpr int A_SZ  = NT * A_STR;    // 6208
constexpr int Q_SZ  = NT * Q_STR;    // 18496
constexpr int W_SZ  = 8 * W_STR;     // 2368
constexpr int RPB_SZ = 225 * NHEADS; // 675
constexpr int SMEM_FLOATS = A_SZ + Q_SZ + W_SZ + RPB_SZ;  // 27747 -> 110988 B

// LayerNorm over 96 cols, 4 threads per row (group via shfl).
__device__ __forceinline__ void ln_rows(float* buf, int stride,
                                        const float* __restrict__ g,
                                        const float* __restrict__ b, int tid) {
  int n = tid >> 2, q = tid & 3;
  float s = 0.f, s2 = 0.f;
#pragma unroll
  for (int j = 0; j < 24; ++j) {
    float v = buf[n * stride + q + 4 * j];
    s += v; s2 += v * v;
  }
  s  += __shfl_xor_sync(0xffffffffu, s, 1);
  s  += __shfl_xor_sync(0xffffffffu, s, 2);
  s2 += __shfl_xor_sync(0xffffffffu, s2, 1);
  s2 += __shfl_xor_sync(0xffffffffu, s2, 2);
  float mu  = s * (1.f / 96.f);
  float var = s2 * (1.f / 96.f) - mu * mu;
  float rs  = rsqrtf(var + LN_EPS);
#pragma unroll
  for (int j = 0; j < 24; ++j) {
    int c = q + 4 * j;
    float v = buf[n * stride + c];
    buf[n * stride + c] = (v - mu) * rs * g[c] + b[c];
  }
}

// out[64][OUTC] = src[64][K] @ w[OUTC][K]^T + bias, optional exact GELU.
// Weights staged through smem in K-chunks of 8. Thread tile: 4 rows x OUTC/16 cols.
template <int OUTC, int K, int ACT>
__device__ __forceinline__ void gemm(const float* __restrict__ src, int sstr, int soff,
                                     float* dst, int dstr, int doff,
                                     const float* __restrict__ w,
                                     const float* __restrict__ bias,
                                     float* Ws, int tid) {
  constexpr int CPT = OUTC / 16;
  const int ty = tid >> 4, tx = tid & 15;
  float acc[4][CPT];
#pragma unroll
  for (int r = 0; r < 4; ++r)
#pragma unroll
    for (int c = 0; c < CPT; ++c) acc[r][c] = 0.f;

  for (int k0 = 0; k0 < K; k0 += 8) {
    for (int i = tid; i < OUTC * 8; i += THREADS) {
      int c = i >> 3, kk = i & 7;
      Ws[kk * W_STR + c] = w[c * K + k0 + kk];
    }
    __syncthreads();
#pragma unroll
    for (int kk = 0; kk < 8; ++kk) {
      float a[4], bb[CPT];
#pragma unroll
      for (int r = 0; r < 4; ++r) a[r] = src[(ty * 4 + r) * sstr + soff + k0 + kk];
#pragma unroll
      for (int c = 0; c < CPT; ++c) bb[c] = Ws[kk * W_STR + tx + c * 16];
#pragma unroll
      for (int r = 0; r < 4; ++r)
#pragma unroll
        for (int c = 0; c < CPT; ++c) acc[r][c] = fmaf(a[r], bb[c], acc[r][c]);
    }
    __syncthreads();
  }
#pragma unroll
  for (int c = 0; c < CPT; ++c) {
    int col = tx + c * 16;
    float bv = bias[col];
#pragma unroll
    for (int r = 0; r < 4; ++r) {
      float v = acc[r][c] + bv;
      if (ACT == 1) v = 0.5f * v * (1.f + erff(v * 0.70710678118654752f));
      dst[(ty * 4 + r) * dstr + doff + col] = v;
    }
  }
  __syncthreads();
}

__global__ void __launch_bounds__(THREADS, 2)
swin_kernel(const float* __restrict__ x,
            const float* __restrict__ qkv_w, const float* __restrict__ qkv_b,
            const float* __restrict__ proj_w, const float* __restrict__ proj_b,
            const float* __restrict__ rpb,
            const float* __restrict__ n1g, const float* __restrict__ n1b,
            const float* __restrict__ n2g, const float* __restrict__ n2b,
            const float* __restrict__ fc1_w, const float* __restrict__ fc1_b,
            const float* __restrict__ fc2_w, const float* __restrict__ fc2_b,
            float* __restrict__ out) {
  extern __shared__ float sm[];
  float* A    = sm;            // 64 x 97  : x window / xln / attn-out / final
  float* Q    = A + A_SZ;      // 64 x 289 : qkv, then proj-out(0..95) + mlp-hidden(97..288)
  float* Ws   = Q + Q_SZ;      // 8 x 296  : staged weight chunk
  float* rpbs = Ws + W_SZ;     // 675      : rel-pos bias table

  const int tid = threadIdx.x;
  const int wid = blockIdx.x;
  const int b  = wid >> 10;
  const int wh = (wid >> 5) & 31;
  const int ww = wid & 31;
  const float* xw = x + ((size_t)b * CD) * 65536 + (size_t)(wh * 8) * 256 + ww * 8;

  for (int i = tid; i < RPB_SZ; i += THREADS) rpbs[i] = rpb[i];
  for (int i = tid; i < CD * NT; i += THREADS) {
    int c = i >> 6, n = i & 63;
    A[n * A_STR + c] = xw[(size_t)c * 65536 + (n >> 3) * 256 + (n & 7)];
  }
  __syncthreads();

  ln_rows(A, A_STR, n1g, n1b, tid);
  __syncthreads();

  // QKV: 64x288, K=96. layout: col = s*96 + h*32 + d
  gemm<288, 96, 0>(A, A_STR, 0, Q, Q_STR, 0, qkv_w, qkv_b, Ws, tid);

  // ---- windowed attention: 4 threads per (row n), per head ----
  {
    const int n = tid >> 2, g = tid & 3;
    const int i1 = n >> 3, j1 = n & 7;
#pragma unroll
    for (int h = 0; h < NHEADS; ++h) {
      float qr[HD];
#pragma unroll
      for (int d = 0; d < HD; ++d)
        qr[d] = Q[n * Q_STR + h * 32 + d] * 0.17677669529663687f;  // 1/sqrt(32)
      float s[16];
#pragma unroll
      for (int mm = 0; mm < 16; ++mm) {
        int m = g * 16 + mm;
        float dot = 0.f;
#pragma unroll
        for (int d = 0; d < HD; ++d)
          dot = fmaf(qr[d], Q[m * Q_STR + 96 + h * 32 + d], dot);
        int ridx = (i1 - (m >> 3) + 7) * 15 + (j1 - (m & 7) + 7);
        s[mm] = dot + rpbs[ridx * 3 + h];
      }
      float mx = s[0];
#pragma unroll
      for (int mm = 1; mm < 16; ++mm) mx = fmaxf(mx, s[mm]);
      mx = fmaxf(mx, __shfl_xor_sync(0xffffffffu, mx, 1));
      mx = fmaxf(mx, __shfl_xor_sync(0xffffffffu, mx, 2));
      float sum = 0.f;
#pragma unroll
      for (int mm = 0; mm < 16; ++mm) { s[mm] = __expf(s[mm] - mx); sum += s[mm]; }
      sum += __shfl_xor_sync(0xffffffffu, sum, 1);
      sum += __shfl_xor_sync(0xffffffffu, sum, 2);
      float inv = 1.f / sum;
#pragma unroll
      for (int mm = 0; mm < 16; ++mm) s[mm] *= inv;

      float acc[HD];
#pragma unroll
      for (int d = 0; d < HD; ++d) acc[d] = 0.f;
#pragma unroll
      for (int mm = 0; mm < 16; ++mm) {
        int m = g * 16 + mm;
        float p = s[mm];
#pragma unroll
        for (int d = 0; d < HD; ++d)
          acc[d] = fmaf(p, Q[m * Q_STR + 192 + h * 32 + d], acc[d]);
      }
#pragma unroll
      for (int d = 0; d < HD; ++d) {
        acc[d] += __shfl_xor_sync(0xffffffffu, acc[d], 1);
        acc[d] += __shfl_xor_sync(0xffffffffu, acc[d], 2);
        if ((d >> 3) == g) A[n * A_STR + h * 32 + d] = acc[d];  // attn out -> A
      }
    }
  }
  __syncthreads();

  // proj: A(attn) -> Q[0..95]
  gemm<96, 96, 0>(A, A_STR, 0, Q, Q_STR, 0, proj_w, proj_b, Ws, tid);
  ln_rows(Q, Q_STR, n2g, n2b, tid);
  __syncthreads();
  // fc1 + exact gelu: Q[0..95] -> Q[97..288]
  gemm<192, 96, 1>(Q, Q_STR, 0, Q, Q_STR, 97, fc1_w, fc1_b, Ws, tid);
  // fc2: Q[97..288] -> A
  gemm<96, 192, 0>(Q, Q_STR, 97, A, A_STR, 0, fc2_w, fc2_b, Ws, tid);

  // residual + merge back to (B,C,H,W)
  float* ob = out + ((size_t)b * CD) * 65536 + (size_t)(wh * 8) * 256 + ww * 8;
  for (int i = tid; i < CD * NT; i += THREADS) {
    int c = i >> 6, n = i & 63;
    size_t go = (size_t)c * 65536 + (n >> 3) * 256 + (n & 7);
    ob[go] = A[n * A_STR + c] + xw[go];
  }
}

extern "C" void kernel_launch(void* const* d_in, const int* in_sizes, int n_in,
                              void* d_out, int out_size) {
  (void)in_sizes; (void)n_in; (void)out_size;
  cudaFuncSetAttribute(swin_kernel, cudaFuncAttributeMaxDynamicSharedMemorySize,
                       SMEM_FLOATS * (int)sizeof(float));
  swin_kernel<<<8192, THREADS, SMEM_FLOATS * sizeof(float)>>>(
      (const float*)d_in[0],
      (const float*)d_in[1], (const float*)d_in[2],
      (const float*)d_in[3], (const float*)d_in[4],
      (const float*)d_in[5],
      (const float*)d_in[6], (const float*)d_in[7],
      (const float*)d_in[8], (const float*)d_in[9],
      (const float*)d_in[10], (const float*)d_in[11],
      (const float*)d_in[12], (const float*)d_in[13],
      (float*)d_out);
}

// round 2
// speedup vs baseline: 1.2656x; 1.2656x over previous
#include <cuda_runtime.h>
#include <math.h>

#define THREADS 256

constexpr int NT  = 64;    // tokens per window
constexpr int CD  = 96;    // channels
constexpr int NHEADS = 3;
constexpr int HD  = 32;
constexpr float LN_EPS = 1e-5f;

// smem layout (floats)
constexpr int A_STR = 97;
constexpr int Q_STR = 289;
constexpr int S_STR = 68;            // S buffer stride (bank-perfect softmax)
constexpr int W_STR = 296;
constexpr int A_SZ  = NT * A_STR;    // 6208 (also hosts S: 64*68=4352)
constexpr int Q_SZ  = NT * Q_STR;    // 18496
constexpr int W_SZ  = 8 * W_STR;     // 2368
constexpr int RPB_SZ = 225 * NHEADS; // 675
constexpr int SMEM_FLOATS = A_SZ + Q_SZ + W_SZ + RPB_SZ;  // 27747 -> 110988 B

// LayerNorm over 96 cols, 4 threads per row (group via shfl).
__device__ __forceinline__ void ln_rows(float* buf, int stride,
                                        const float* __restrict__ g,
                                        const float* __restrict__ b, int tid) {
  int n = tid >> 2, q = tid & 3;
  float s = 0.f, s2 = 0.f;
#pragma unroll
  for (int j = 0; j < 24; ++j) {
    float v = buf[n * stride + q + 4 * j];
    s += v; s2 += v * v;
  }
  s  += __shfl_xor_sync(0xffffffffu, s, 1);
  s  += __shfl_xor_sync(0xffffffffu, s, 2);
  s2 += __shfl_xor_sync(0xffffffffu, s2, 1);
  s2 += __shfl_xor_sync(0xffffffffu, s2, 2);
  float mu  = s * (1.f / 96.f);
  float var = s2 * (1.f / 96.f) - mu * mu;
  float rs  = rsqrtf(var + LN_EPS);
#pragma unroll
  for (int j = 0; j < 24; ++j) {
    int c = q + 4 * j;
    float v = buf[n * stride + c];
    buf[n * stride + c] = (v - mu) * rs * g[c] + b[c];
  }
}

// out[64][OUTC] = src[64][K] @ w[OUTC][K]^T + bias, optional exact GELU.
template <int OUTC, int K, int ACT>
__device__ __forceinline__ void gemm(const float* __restrict__ src, int sstr, int soff,
                                     float* dst, int dstr, int doff,
                                     const float* __restrict__ w,
                                     const float* __restrict__ bias,
                                     float* Ws, int tid) {
  constexpr int CPT = OUTC / 16;
  const int ty = tid >> 4, tx = tid & 15;
  float acc[4][CPT];
#pragma unroll
  for (int r = 0; r < 4; ++r)
#pragma unroll
    for (int c = 0; c < CPT; ++c) acc[r][c] = 0.f;

  for (int k0 = 0; k0 < K; k0 += 8) {
    for (int i = tid; i < OUTC * 8; i += THREADS) {
      int c = i >> 3, kk = i & 7;
      Ws[kk * W_STR + c] = w[c * K + k0 + kk];
    }
    __syncthreads();
#pragma unroll
    for (int kk = 0; kk < 8; ++kk) {
      float a[4], bb[CPT];
#pragma unroll
      for (int r = 0; r < 4; ++r) a[r] = src[(ty * 4 + r) * sstr + soff + k0 + kk];
#pragma unroll
      for (int c = 0; c < CPT; ++c) bb[c] = Ws[kk * W_STR + tx + c * 16];
#pragma unroll
      for (int r = 0; r < 4; ++r)
#pragma unroll
        for (int c = 0; c < CPT; ++c) acc[r][c] = fmaf(a[r], bb[c], acc[r][c]);
    }
    __syncthreads();
  }
#pragma unroll
  for (int c = 0; c < CPT; ++c) {
    int col = tx + c * 16;
    float bv = bias[col];
#pragma unroll
    for (int r = 0; r < 4; ++r) {
      float v = acc[r][c] + bv;
      if (ACT == 1) v = 0.5f * v * (1.f + erff(v * 0.70710678118654752f));
      dst[(ty * 4 + r) * dstr + doff + col] = v;
    }
  }
  __syncthreads();
}

__global__ void __launch_bounds__(THREADS, 2)
swin_kernel(const float* __restrict__ x,
            const float* __restrict__ qkv_w, const float* __restrict__ qkv_b,
            const float* __restrict__ proj_w, const float* __restrict__ proj_b,
            const float* __restrict__ rpb,
            const float* __restrict__ n1g, const float* __restrict__ n1b,
            const float* __restrict__ n2g, const float* __restrict__ n2b,
            const float* __restrict__ fc1_w, const float* __restrict__ fc1_b,
            const float* __restrict__ fc2_w, const float* __restrict__ fc2_b,
            float* __restrict__ out) {
  extern __shared__ float sm[];
  float* A    = sm;            // 64x97: xln -> S (64x68) -> proj/ln2 -> fc2-out
  float* Q    = A + A_SZ;      // 64x289: qkv -> attn-out in q-cols -> mlp hidden
  float* Ws   = Q + Q_SZ;      // 8x296
  float* rpbs = Ws + W_SZ;     // 675

  const int tid = threadIdx.x;
  const int wid = blockIdx.x;
  const int b  = wid >> 10;
  const int wh = (wid >> 5) & 31;
  const int ww = wid & 31;
  const float* xw = x + ((size_t)b * CD) * 65536 + (size_t)(wh * 8) * 256 + ww * 8;

  for (int i = tid; i < RPB_SZ; i += THREADS) rpbs[i] = rpb[i];
  for (int i = tid; i < CD * NT; i += THREADS) {
    int c = i >> 6, n = i & 63;
    A[n * A_STR + c] = xw[(size_t)c * 65536 + (n >> 3) * 256 + (n & 7)];
  }
  __syncthreads();

  ln_rows(A, A_STR, n1g, n1b, tid);
  __syncthreads();

  // QKV: 64x288, K=96. col = s*96 + h*32 + d
  gemm<288, 96, 0>(A, A_STR, 0, Q, Q_STR, 0, qkv_w, qkv_b, Ws, tid);

  // ---- attention, GEMM-shaped per head; S lives in A (xln is dead) ----
  {
    const int ty = tid >> 4, tx = tid & 15;       // S-gemm mapping
    const int sn = tid >> 2, sg = tid & 3;        // softmax mapping
#pragma unroll
    for (int h = 0; h < NHEADS; ++h) {
      // S[n][m] = scale * q[n].k[m] + bias
      {
        float acc[4][4];
#pragma unroll
        for (int r = 0; r < 4; ++r)
#pragma unroll
          for (int c = 0; c < 4; ++c) acc[r][c] = 0.f;
#pragma unroll
        for (int kk = 0; kk < HD; ++kk) {
          float a[4], bb[4];
#pragma unroll
          for (int r = 0; r < 4; ++r) a[r] = Q[(ty * 4 + r) * Q_STR + h * 32 + kk];
#pragma unroll
          for (int c = 0; c < 4; ++c) bb[c] = Q[(tx + 16 * c) * Q_STR + 96 + h * 32 + kk];
#pragma unroll
          for (int r = 0; r < 4; ++r)
#pragma unroll
            for (int c = 0; c < 4; ++c) acc[r][c] = fmaf(a[r], bb[c], acc[r][c]);
        }
#pragma unroll
        for (int r = 0; r < 4; ++r) {
          int n = ty * 4 + r;
          int i1 = n >> 3, j1 = n & 7;
#pragma unroll
          for (int c = 0; c < 4; ++c) {
            int m = tx + 16 * c;
            int ridx = (i1 - (m >> 3) + 7) * 15 + (j1 - (m & 7) + 7);
            A[n * S_STR + m] = acc[r][c] * 0.17677669529663687f + rpbs[ridx * 3 + h];
          }
        }
      }
      __syncthreads();
      // softmax row sn; this thread owns cols sg + 4*mm (bank-perfect)
      {
        float s[16];
#pragma unroll
        for (int mm = 0; mm < 16; ++mm) s[mm] = A[sn * S_STR + sg + 4 * mm];
        float mx = s[0];
#pragma unroll
        for (int mm = 1; mm < 16; ++mm) mx = fmaxf(mx, s[mm]);
        mx = fmaxf(mx, __shfl_xor_sync(0xffffffffu, mx, 1));
        mx = fmaxf(mx, __shfl_xor_sync(0xffffffffu, mx, 2));
        float sum = 0.f;
#pragma unroll
        for (int mm = 0; mm < 16; ++mm) { s[mm] = __expf(s[mm] - mx); sum += s[mm]; }
        sum += __shfl_xor_sync(0xffffffffu, sum, 1);
        sum += __shfl_xor_sync(0xffffffffu, sum, 2);
        float inv = 1.f / sum;
#pragma unroll
        for (int mm = 0; mm < 16; ++mm) A[sn * S_STR + sg + 4 * mm] = s[mm] * inv;
      }
      __syncthreads();
      // out = S @ V -> overwrite q-slot of head h in Q (cols h*32..h*32+31)
      {
        float acc[4][2];
#pragma unroll
        for (int r = 0; r < 4; ++r) { acc[r][0] = 0.f; acc[r][1] = 0.f; }
#pragma unroll
        for (int kk = 0; kk < NT; ++kk) {
          float a[4], b0, b1;
#pragma unroll
          for (int r = 0; r < 4; ++r) a[r] = A[(ty * 4 + r) * S_STR + kk];
          b0 = Q[kk * Q_STR + 192 + h * 32 + tx];
          b1 = Q[kk * Q_STR + 192 + h * 32 + tx + 16];
#pragma unroll
          for (int r = 0; r < 4; ++r) {
            acc[r][0] = fmaf(a[r], b0, acc[r][0]);
            acc[r][1] = fmaf(a[r], b1, acc[r][1]);
          }
        }
        __syncthreads();  // all S reads done before q-slot overwrite & next-head S write
#pragma unroll
        for (int r = 0; r < 4; ++r) {
          Q[(ty * 4 + r) * Q_STR + h * 32 + tx]      = acc[r][0];
          Q[(ty * 4 + r) * Q_STR + h * 32 + tx + 16] = acc[r][1];
        }
      }
      __syncthreads();
    }
  }

  // proj: Q[0..95] -> A[0..95]
  gemm<96, 96, 0>(Q, Q_STR, 0, A, A_STR, 0, proj_w, proj_b, Ws, tid);
  ln_rows(A, A_STR, n2g, n2b, tid);
  __syncthreads();
  // fc1 + exact gelu: A[0..95] -> Q[0..191]
  gemm<192, 96, 1>(A, A_STR, 0, Q, Q_STR, 0, fc1_w, fc1_b, Ws, tid);
  // fc2: Q[0..191] -> A[0..95]
  gemm<96, 192, 0>(Q, Q_STR, 0, A, A_STR, 0, fc2_w, fc2_b, Ws, tid);

  // residual + merge back to (B,C,H,W)
  float* ob = out + ((size_t)b * CD) * 65536 + (size_t)(wh * 8) * 256 + ww * 8;
  for (int i = tid; i < CD * NT; i += THREADS) {
    int c = i >> 6, n = i & 63;
    size_t go = (size_t)c * 65536 + (n >> 3) * 256 + (n & 7);
    ob[go] = A[n * A_STR + c] + xw[go];
  }
}

extern "C" void kernel_launch(void* const* d_in, const int* in_sizes, int n_in,
                              void* d_out, int out_size) {
  (void)in_sizes; (void)n_in; (void)out_size;
  cudaFuncSetAttribute(swin_kernel, cudaFuncAttributeMaxDynamicSharedMemorySize,
                       SMEM_FLOATS * (int)sizeof(float));
  swin_kernel<<<8192, THREADS, SMEM_FLOATS * sizeof(float)>>>(
      (const float*)d_in[0],
      (const float*)d_in[1], (const float*)d_in[2],
      (const float*)d_in[3], (const float*)d_in[4],
      (const float*)d_in[5],
      (const float*)d_in[6], (const float*)d_in[7],
      (const float*)d_in[8], (const float*)d_in[9],
      (const float*)d_in[10], (const float*)d_in[11],
      (const float*)d_in[12], (const float*)d_in[13],
      (float*)d_out);
}

// round 3
// speedup vs baseline: 1.4410x; 1.1386x over previous
#include <cuda_runtime.h>
#include <math.h>

#define THREADS 256

constexpr int NT = 64, CDIM = 96, NHEADS = 3, HD = 32;
constexpr float LN_EPS = 1e-5f;
constexpr float SCALE = 0.17677669529663687f;  // 1/sqrt(32)

// smem layout (floats) — all strides multiples of 4 (16B-aligned rows)
constexpr int XA_STR = 100;   // x window / ln1 / S-buffer(flat) / proj-out / ln2
constexpr int QB_STR = 100;   // q / attn-out / fc2-out
constexpr int KVT_STR = 68;   // k^T rows 0..95, v^T rows 96..191 ; later MLP hidden
constexpr int S_STR  = 68;
constexpr int H_STR  = 196;   // hidden 64x192 lives in KVT region
constexpr int XA_SZ  = 64 * XA_STR;    // 6400
constexpr int QB_SZ  = 64 * QB_STR;    // 6400
constexpr int KVT_SZ = 192 * KVT_STR;  // 13056 (>= 64*196 = 12544)
constexpr int WS_HALF = 192 * 4;       // one weight stage buffer (float4 per col)
constexpr int WS_SZ  = 2 * WS_HALF;    // 1536 (double buffered)
constexpr int RPB_SZ = 225 * NHEADS;   // 675
constexpr int SMEM_FLOATS = XA_SZ + QB_SZ + KVT_SZ + WS_SZ + RPB_SZ;  // 28067 -> 112268 B

__device__ __forceinline__ float dot4(float4 a, float4 b, float acc) {
  acc = fmaf(a.x, b.x, acc); acc = fmaf(a.y, b.y, acc);
  acc = fmaf(a.z, b.z, acc); acc = fmaf(a.w, b.w, acc);
  return acc;
}
__device__ __forceinline__ float getc(float4 v, int j) {
  return j == 0 ? v.x : (j == 1 ? v.y : (j == 2 ? v.z : v.w));
}

// LayerNorm over 96 cols, 4 threads per row.
__device__ __forceinline__ void ln_rows(float* buf, int stride,
                                        const float* __restrict__ g,
                                        const float* __restrict__ b, int tid) {
  int n = tid >> 2, q = tid & 3;
  float s = 0.f, s2 = 0.f;
#pragma unroll
  for (int j = 0; j < 24; ++j) {
    float v = buf[n * stride + q + 4 * j];
    s += v; s2 += v * v;
  }
  s  += __shfl_xor_sync(0xffffffffu, s, 1);
  s  += __shfl_xor_sync(0xffffffffu, s, 2);
  s2 += __shfl_xor_sync(0xffffffffu, s2, 1);
  s2 += __shfl_xor_sync(0xffffffffu, s2, 2);
  float mu  = s * (1.f / 96.f);
  float var = s2 * (1.f / 96.f) - mu * mu;
  float rs  = rsqrtf(var + LN_EPS);
#pragma unroll
  for (int j = 0; j < 24; ++j) {
    int c = q + 4 * j;
    float v = buf[n * stride + c];
    buf[n * stride + c] = (v - mu) * rs * g[c] + b[c];
  }
}

// out[64][OUTC] = src[64][K] @ w[OUTC][K]^T + bias.
// EPI: 0 = plain store to dst, 1 = exact GELU store, 2 = transposed store (dst[col][row], stride 68).
// Thread tile: 8 rows (ty=tid>>5) x OUTC/32 cols (tx=tid&31). K chunked by 4, weights
// double-buffer staged in Ws as float4-per-col. Ends with __syncthreads.
template <int OUTC, int K, int EPI>
__device__ __forceinline__ void gemm(const float* __restrict__ src, int sstr, int soff,
                                     float* __restrict__ dst, int dstr, int doff,
                                     const float* __restrict__ w,
                                     const float* __restrict__ bias,
                                     float* __restrict__ Ws, int tid) {
  constexpr int CPT = OUTC / 32;
  constexpr int NI = K / 4;
  const int ty = tid >> 5, tx = tid & 31;
  float acc[8][CPT];
#pragma unroll
  for (int r = 0; r < 8; ++r)
#pragma unroll
    for (int c = 0; c < CPT; ++c) acc[r][c] = 0.f;

  if (tid < OUTC) ((float4*)Ws)[tid] = *(const float4*)&w[tid * K];
  __syncthreads();

  for (int i = 0; i < NI; ++i) {
    const float4* cur = (const float4*)(Ws + (i & 1) * WS_HALF);
    if (i + 1 < NI && tid < OUTC)
      ((float4*)(Ws + ((i + 1) & 1) * WS_HALF))[tid] = *(const float4*)&w[tid * K + (i + 1) * 4];
    float4 bb[CPT];
#pragma unroll
    for (int c = 0; c < CPT; ++c) bb[c] = cur[tx + 32 * c];
#pragma unroll
    for (int r = 0; r < 8; ++r) {
      float4 av = *(const float4*)&src[(8 * ty + r) * sstr + soff + i * 4];
#pragma unroll
      for (int c = 0; c < CPT; ++c) acc[r][c] = dot4(av, bb[c], acc[r][c]);
    }
    __syncthreads();
  }

#pragma unroll
  for (int c = 0; c < CPT; ++c) {
    int col = tx + 32 * c;
    float bv = bias[col];
    if (EPI == 2) {
      float4 lo, hi;
      lo.x = acc[0][c] + bv; lo.y = acc[1][c] + bv; lo.z = acc[2][c] + bv; lo.w = acc[3][c] + bv;
      hi.x = acc[4][c] + bv; hi.y = acc[5][c] + bv; hi.z = acc[6][c] + bv; hi.w = acc[7][c] + bv;
      *(float4*)&dst[col * KVT_STR + 8 * ty]     = lo;
      *(float4*)&dst[col * KVT_STR + 8 * ty + 4] = hi;
    } else {
#pragma unroll
      for (int r = 0; r < 8; ++r) {
        float v = acc[r][c] + bv;
        if (EPI == 1) v = 0.5f * v * (1.f + erff(v * 0.70710678118654752f));
        dst[(8 * ty + r) * dstr + doff + col] = v;
      }
    }
  }
  __syncthreads();
}

__global__ void __launch_bounds__(THREADS, 2)
swin_kernel(const float* __restrict__ x,
            const float* __restrict__ qkv_w, const float* __restrict__ qkv_b,
            const float* __restrict__ proj_w, const float* __restrict__ proj_b,
            const float* __restrict__ rpb,
            const float* __restrict__ n1g, const float* __restrict__ n1b,
            const float* __restrict__ n2g, const float* __restrict__ n2b,
            const float* __restrict__ fc1_w, const float* __restrict__ fc1_b,
            const float* __restrict__ fc2_w, const float* __restrict__ fc2_b,
            float* __restrict__ out) {
  extern __shared__ float sm[];
  float* XA   = sm;              // 64x100 ; also S (flat 64x68) ; proj-out/ln2
  float* QB   = XA + XA_SZ;      // 64x100 ; q -> attn-out -> fc2-out
  float* KVT  = QB + QB_SZ;      // 192x68 ; kT/vT -> later hidden 64x196
  float* Ws   = KVT + KVT_SZ;    // 2x768
  float* rpbs = Ws + WS_SZ;      // 675
  float* Sb   = XA;              // S buffer aliases XA (ln-x dead by then)
  float* Hid  = KVT;             // hidden aliases KVT

  const int tid = threadIdx.x;
  const int wid = blockIdx.x;
  const int b  = wid >> 10;
  const int wh = (wid >> 5) & 31;
  const int ww = wid & 31;
  const float* xw = x + ((size_t)b * CDIM) * 65536 + (size_t)(wh * 8) * 256 + ww * 8;

  for (int i = tid; i < RPB_SZ; i += THREADS) rpbs[i] = rpb[i];
  for (int i = tid; i < CDIM * NT; i += THREADS) {
    int c = i >> 6, n = i & 63;
    XA[n * XA_STR + c] = xw[(size_t)c * 65536 + (n >> 3) * 256 + (n & 7)];
  }
  __syncthreads();

  ln_rows(XA, XA_STR, n1g, n1b, tid);
  __syncthreads();

  // q -> QB ; k,v -> KVT transposed (rows = channel, cols = token)
  gemm<96, 96, 0>(XA, XA_STR, 0, QB, QB_STR, 0, qkv_w, qkv_b, Ws, tid);
  gemm<192, 96, 2>(XA, XA_STR, 0, KVT, 0, 0, qkv_w + 96 * 96, qkv_b + 96, Ws, tid);

  // ---- attention ----
  for (int h = 0; h < NHEADS; ++h) {
    // S[n][m] = scale*(q.k) + bias ; tile: 4 rows (ty) x 4 consecutive m (tx)
    {
      const int ty = tid >> 4, tx = tid & 15;
      float acc[4][4];
#pragma unroll
      for (int r = 0; r < 4; ++r)
#pragma unroll
        for (int c = 0; c < 4; ++c) acc[r][c] = 0.f;
#pragma unroll
      for (int k0 = 0; k0 < HD; k0 += 4) {
        float4 qa[4];
#pragma unroll
        for (int r = 0; r < 4; ++r)
          qa[r] = *(const float4*)&QB[(4 * ty + r) * QB_STR + h * 32 + k0];
#pragma unroll
        for (int j = 0; j < 4; ++j) {
          float4 kb = *(const float4*)&KVT[(h * 32 + k0 + j) * KVT_STR + 4 * tx];
#pragma unroll
          for (int r = 0; r < 4; ++r) {
            float qv = getc(qa[r], j);
            acc[r][0] = fmaf(qv, kb.x, acc[r][0]);
            acc[r][1] = fmaf(qv, kb.y, acc[r][1]);
            acc[r][2] = fmaf(qv, kb.z, acc[r][2]);
            acc[r][3] = fmaf(qv, kb.w, acc[r][3]);
          }
        }
      }
#pragma unroll
      for (int r = 0; r < 4; ++r) {
        int n = 4 * ty + r, i1 = n >> 3, j1 = n & 7;
        float4 sv;
#pragma unroll
        for (int c = 0; c < 4; ++c) {
          int m = 4 * tx + c;
          int ridx = (i1 - (m >> 3) + 7) * 15 + (j1 - (m & 7) + 7);
          float v = acc[r][c] * SCALE + rpbs[ridx * 3 + h];
          if (c == 0) sv.x = v; else if (c == 1) sv.y = v; else if (c == 2) sv.z = v; else sv.w = v;
        }
        *(float4*)&Sb[n * S_STR + 4 * tx] = sv;
      }
    }
    __syncthreads();
    // softmax: 4 threads per row, float4 IO
    {
      const int sn = tid >> 2, sg = tid & 3;
      float s[16];
#pragma unroll
      for (int q = 0; q < 4; ++q) {
        float4 v = *(const float4*)&Sb[sn * S_STR + sg * 16 + 4 * q];
        s[4 * q] = v.x; s[4 * q + 1] = v.y; s[4 * q + 2] = v.z; s[4 * q + 3] = v.w;
      }
      float mx = s[0];
#pragma unroll
      for (int m = 1; m < 16; ++m) mx = fmaxf(mx, s[m]);
      mx = fmaxf(mx, __shfl_xor_sync(0xffffffffu, mx, 1));
      mx = fmaxf(mx, __shfl_xor_sync(0xffffffffu, mx, 2));
      float sum = 0.f;
#pragma unroll
      for (int m = 0; m < 16; ++m) { s[m] = __expf(s[m] - mx); sum += s[m]; }
      sum += __shfl_xor_sync(0xffffffffu, sum, 1);
      sum += __shfl_xor_sync(0xffffffffu, sum, 2);
      float inv = 1.f / sum;
#pragma unroll
      for (int q = 0; q < 4; ++q) {
        float4 v;
        v.x = s[4 * q] * inv; v.y = s[4 * q + 1] * inv;
        v.z = s[4 * q + 2] * inv; v.w = s[4 * q + 3] * inv;
        *(float4*)&Sb[sn * S_STR + sg * 16 + 4 * q] = v;
      }
    }
    __syncthreads();
    // out = S @ V : tile 4 rows (ty) x 2 d-cols (tx, tx+16) -> QB q-slot of head h
    {
      const int ty = tid >> 4, tx = tid & 15;
      float a0[4] = {0.f, 0.f, 0.f, 0.f}, a1[4] = {0.f, 0.f, 0.f, 0.f};
#pragma unroll
      for (int k0 = 0; k0 < NT; k0 += 4) {
        float4 vb0 = *(const float4*)&KVT[(96 + h * 32 + tx) * KVT_STR + k0];
        float4 vb1 = *(const float4*)&KVT[(96 + h * 32 + tx + 16) * KVT_STR + k0];
#pragma unroll
        for (int r = 0; r < 4; ++r) {
          float4 sa = *(const float4*)&Sb[(4 * ty + r) * S_STR + k0];
          a0[r] = dot4(sa, vb0, a0[r]);
          a1[r] = dot4(sa, vb1, a1[r]);
        }
      }
#pragma unroll
      for (int r = 0; r < 4; ++r) {
        QB[(4 * ty + r) * QB_STR + h * 32 + tx]      = a0[r];
        QB[(4 * ty + r) * QB_STR + h * 32 + tx + 16] = a1[r];
      }
    }
    __syncthreads();
  }

  // proj: QB(attn) -> XA ; ln2 ; fc1+gelu -> Hid ; fc2 -> QB
  gemm<96, 96, 0>(QB, QB_STR, 0, XA, XA_STR, 0, proj_w, proj_b, Ws, tid);
  ln_rows(XA, XA_STR, n2g, n2b, tid);
  __syncthreads();
  gemm<192, 96, 1>(XA, XA_STR, 0, Hid, H_STR, 0, fc1_w, fc1_b, Ws, tid);
  gemm<96, 192, 0>(Hid, H_STR, 0, QB, QB_STR, 0, fc2_w, fc2_b, Ws, tid);

  // residual + window merge
  float* ob = out + ((size_t)b * CDIM) * 65536 + (size_t)(wh * 8) * 256 + ww * 8;
  for (int i = tid; i < CDIM * NT; i += THREADS) {
    int c = i >> 6, n = i & 63;
    size_t go = (size_t)c * 65536 + (n >> 3) * 256 + (n & 7);
    ob[go] = QB[n * QB_STR + c] + xw[go];
  }
}

extern "C" void kernel_launch(void* const* d_in, const int* in_sizes, int n_in,
                              void* d_out, int out_size) {
  (void)in_sizes; (void)n_in; (void)out_size;
  cudaFuncSetAttribute(swin_kernel, cudaFuncAttributeMaxDynamicSharedMemorySize,
                       SMEM_FLOATS * (int)sizeof(float));
  swin_kernel<<<8192, THREADS, SMEM_FLOATS * sizeof(float)>>>(
      (const float*)d_in[0],
      (const float*)d_in[1], (const float*)d_in[2],
      (const float*)d_in[3], (const float*)d_in[4],
      (const float*)d_in[5],
      (const float*)d_in[6], (const float*)d_in[7],
      (const float*)d_in[8], (const float*)d_in[9],
      (const float*)d_in[10], (const float*)d_in[11],
      (const float*)d_in[12], (const float*)d_in[13],
      (float*)d_out);
}

// round 4
// speedup vs baseline: 1.4417x; 1.0005x over previous
#include <cuda_runtime.h>
#include <math.h>

#define THREADS 256

constexpr int NT = 64, CDIM = 96, NHEADS = 3, HD = 32;
constexpr float LN_EPS = 1e-5f;
constexpr float SCALE = 0.17677669529663687f;  // 1/sqrt(32)

// smem layout (floats) — all strides multiples of 4 (16B-aligned rows)
constexpr int XA_STR = 100;   // x window / ln1 / S-buffer(flat) / proj-out / ln2
constexpr int QB_STR = 100;   // q / attn-out / fc2-out
constexpr int KVT_STR = 68;   // k^T rows 0..95, v^T rows 96..191 ; later MLP hidden
constexpr int S_STR  = 68;
constexpr int H_STR  = 196;   // hidden 64x192 lives in KVT region
constexpr int XA_SZ  = 64 * XA_STR;    // 6400
constexpr int QB_SZ  = 64 * QB_STR;    // 6400
constexpr int KVT_SZ = 192 * KVT_STR;  // 13056 (>= 64*196 = 12544)
constexpr int WS_HALF = 192 * 4;       // one weight stage buffer (float4 per col)
constexpr int WS_SZ  = 2 * WS_HALF;    // 1536 (double buffered)
constexpr int RPB_SZ = 225 * NHEADS;   // 675
constexpr int SMEM_FLOATS = XA_SZ + QB_SZ + KVT_SZ + WS_SZ + RPB_SZ;  // 28067 -> 112268 B

__device__ __forceinline__ float dot4(float4 a, float4 b, float acc) {
  acc = fmaf(a.x, b.x, acc); acc = fmaf(a.y, b.y, acc);
  acc = fmaf(a.z, b.z, acc); acc = fmaf(a.w, b.w, acc);
  return acc;
}
__device__ __forceinline__ float getc(float4 v, int j) {
  return j == 0 ? v.x : (j == 1 ? v.y : (j == 2 ? v.z : v.w));
}

// LayerNorm over 96 cols, 4 threads per row.
__device__ __forceinline__ void ln_rows(float* buf, int stride,
                                        const float* __restrict__ g,
                                        const float* __restrict__ b, int tid) {
  int n = tid >> 2, q = tid & 3;
  float s = 0.f, s2 = 0.f;
#pragma unroll
  for (int j = 0; j < 24; ++j) {
    float v = buf[n * stride + q + 4 * j];
    s += v; s2 += v * v;
  }
  s  += __shfl_xor_sync(0xffffffffu, s, 1);
  s  += __shfl_xor_sync(0xffffffffu, s, 2);
  s2 += __shfl_xor_sync(0xffffffffu, s2, 1);
  s2 += __shfl_xor_sync(0xffffffffu, s2, 2);
  float mu  = s * (1.f / 96.f);
  float var = s2 * (1.f / 96.f) - mu * mu;
  float rs  = rsqrtf(var + LN_EPS);
#pragma unroll
  for (int j = 0; j < 24; ++j) {
    int c = q + 4 * j;
    float v = buf[n * stride + c];
    buf[n * stride + c] = (v - mu) * rs * g[c] + b[c];
  }
}

// out[64][OUTC] = src[64][K] @ w[OUTC][K]^T + bias.
// EPI: 0 = plain store to dst, 1 = exact GELU store, 2 = transposed store (dst[col][row], stride 68).
// Thread tile: 8 rows (ty=tid>>5) x OUTC/32 cols (tx=tid&31). K chunked by 4, weights
// double-buffer staged in Ws as float4-per-col. Ends with __syncthreads.
template <int OUTC, int K, int EPI>
__device__ __forceinline__ void gemm(const float* __restrict__ src, int sstr, int soff,
                                     float* __restrict__ dst, int dstr, int doff,
                                     const float* __restrict__ w,
                                     const float* __restrict__ bias,
                                     float* __restrict__ Ws, int tid) {
  constexpr int CPT = OUTC / 32;
  constexpr int NI = K / 4;
  const int ty = tid >> 5, tx = tid & 31;
  float acc[8][CPT];
#pragma unroll
  for (int r = 0; r < 8; ++r)
#pragma unroll
    for (int c = 0; c < CPT; ++c) acc[r][c] = 0.f;

  if (tid < OUTC) ((float4*)Ws)[tid] = *(const float4*)&w[tid * K];
  __syncthreads();

  for (int i = 0; i < NI; ++i) {
    const float4* cur = (const float4*)(Ws + (i & 1) * WS_HALF);
    if (i + 1 < NI && tid < OUTC)
      ((float4*)(Ws + ((i + 1) & 1) * WS_HALF))[tid] = *(const float4*)&w[tid * K + (i + 1) * 4];
    float4 bb[CPT];
#pragma unroll
    for (int c = 0; c < CPT; ++c) bb[c] = cur[tx + 32 * c];
#pragma unroll
    for (int r = 0; r < 8; ++r) {
      float4 av = *(const float4*)&src[(8 * ty + r) * sstr + soff + i * 4];
#pragma unroll
      for (int c = 0; c < CPT; ++c) acc[r][c] = dot4(av, bb[c], acc[r][c]);
    }
    __syncthreads();
  }

#pragma unroll
  for (int c = 0; c < CPT; ++c) {
    int col = tx + 32 * c;
    float bv = bias[col];
    if (EPI == 2) {
      float4 lo, hi;
      lo.x = acc[0][c] + bv; lo.y = acc[1][c] + bv; lo.z = acc[2][c] + bv; lo.w = acc[3][c] + bv;
      hi.x = acc[4][c] + bv; hi.y = acc[5][c] + bv; hi.z = acc[6][c] + bv; hi.w = acc[7][c] + bv;
      *(float4*)&dst[col * KVT_STR + 8 * ty]     = lo;
      *(float4*)&dst[col * KVT_STR + 8 * ty + 4] = hi;
    } else {
#pragma unroll
      for (int r = 0; r < 8; ++r) {
        float v = acc[r][c] + bv;
        if (EPI == 1) v = 0.5f * v * (1.f + erff(v * 0.70710678118654752f));
        dst[(8 * ty + r) * dstr + doff + col] = v;
      }
    }
  }
  __syncthreads();
}

__global__ void __launch_bounds__(THREADS, 2)
swin_kernel(const float* __restrict__ x,
            const float* __restrict__ qkv_w, const float* __restrict__ qkv_b,
            const float* __restrict__ proj_w, const float* __restrict__ proj_b,
            const float* __restrict__ rpb,
            const float* __restrict__ n1g, const float* __restrict__ n1b,
            const float* __restrict__ n2g, const float* __restrict__ n2b,
            const float* __restrict__ fc1_w, const float* __restrict__ fc1_b,
            const float* __restrict__ fc2_w, const float* __restrict__ fc2_b,
            float* __restrict__ out) {
  extern __shared__ float sm[];
  float* XA   = sm;              // 64x100 ; also S (flat 64x68) ; proj-out/ln2
  float* QB   = XA + XA_SZ;      // 64x100 ; q -> attn-out -> fc2-out
  float* KVT  = QB + QB_SZ;      // 192x68 ; kT/vT -> later hidden 64x196
  float* Ws   = KVT + KVT_SZ;    // 2x768
  float* rpbs = Ws + WS_SZ;      // 675
  float* Sb   = XA;              // S buffer aliases XA (ln-x dead by then)
  float* Hid  = KVT;             // hidden aliases KVT

  const int tid = threadIdx.x;
  const int wid = blockIdx.x;
  const int b  = wid >> 10;
  const int wh = (wid >> 5) & 31;
  const int ww = wid & 31;
  const float* xw = x + ((size_t)b * CDIM) * 65536 + (size_t)(wh * 8) * 256 + ww * 8;

  for (int i = tid; i < RPB_SZ; i += THREADS) rpbs[i] = rpb[i];
  for (int i = tid; i < CDIM * NT; i += THREADS) {
    int c = i >> 6, n = i & 63;
    XA[n * XA_STR + c] = xw[(size_t)c * 65536 + (n >> 3) * 256 + (n & 7)];
  }
  __syncthreads();

  ln_rows(XA, XA_STR, n1g, n1b, tid);
  __syncthreads();

  // q -> QB ; k,v -> KVT transposed (rows = channel, cols = token)
  gemm<96, 96, 0>(XA, XA_STR, 0, QB, QB_STR, 0, qkv_w, qkv_b, Ws, tid);
  gemm<192, 96, 2>(XA, XA_STR, 0, KVT, 0, 0, qkv_w + 96 * 96, qkv_b + 96, Ws, tid);

  // ---- attention ----
  for (int h = 0; h < NHEADS; ++h) {
    // S[n][m] = scale*(q.k) + bias ; tile: 4 rows (ty) x 4 consecutive m (tx)
    {
      const int ty = tid >> 4, tx = tid & 15;
      float acc[4][4];
#pragma unroll
      for (int r = 0; r < 4; ++r)
#pragma unroll
        for (int c = 0; c < 4; ++c) acc[r][c] = 0.f;
#pragma unroll
      for (int k0 = 0; k0 < HD; k0 += 4) {
        float4 qa[4];
#pragma unroll
        for (int r = 0; r < 4; ++r)
          qa[r] = *(const float4*)&QB[(4 * ty + r) * QB_STR + h * 32 + k0];
#pragma unroll
        for (int j = 0; j < 4; ++j) {
          float4 kb = *(const float4*)&KVT[(h * 32 + k0 + j) * KVT_STR + 4 * tx];
#pragma unroll
          for (int r = 0; r < 4; ++r) {
            float qv = getc(qa[r], j);
            acc[r][0] = fmaf(qv, kb.x, acc[r][0]);
            acc[r][1] = fmaf(qv, kb.y, acc[r][1]);
            acc[r][2] = fmaf(qv, kb.z, acc[r][2]);
            acc[r][3] = fmaf(qv, kb.w, acc[r][3]);
          }
        }
      }
#pragma unroll
      for (int r = 0; r < 4; ++r) {
        int n = 4 * ty + r, i1 = n >> 3, j1 = n & 7;
        float4 sv;
#pragma unroll
        for (int c = 0; c < 4; ++c) {
          int m = 4 * tx + c;
          int ridx = (i1 - (m >> 3) + 7) * 15 + (j1 - (m & 7) + 7);
          float v = acc[r][c] * SCALE + rpbs[ridx * 3 + h];
          if (c == 0) sv.x = v; else if (c == 1) sv.y = v; else if (c == 2) sv.z = v; else sv.w = v;
        }
        *(float4*)&Sb[n * S_STR + 4 * tx] = sv;
      }
    }
    __syncthreads();
    // softmax: 4 threads per row, float4 IO
    {
      const int sn = tid >> 2, sg = tid & 3;
      float s[16];
#pragma unroll
      for (int q = 0; q < 4; ++q) {
        float4 v = *(const float4*)&Sb[sn * S_STR + sg * 16 + 4 * q];
        s[4 * q] = v.x; s[4 * q + 1] = v.y; s[4 * q + 2] = v.z; s[4 * q + 3] = v.w;
      }
      float mx = s[0];
#pragma unroll
      for (int m = 1; m < 16; ++m) mx = fmaxf(mx, s[m]);
      mx = fmaxf(mx, __shfl_xor_sync(0xffffffffu, mx, 1));
      mx = fmaxf(mx, __shfl_xor_sync(0xffffffffu, mx, 2));
      float sum = 0.f;
#pragma unroll
      for (int m = 0; m < 16; ++m) { s[m] = __expf(s[m] - mx); sum += s[m]; }
      sum += __shfl_xor_sync(0xffffffffu, sum, 1);
      sum += __shfl_xor_sync(0xffffffffu, sum, 2);
      float inv = 1.f / sum;
#pragma unroll
      for (int q = 0; q < 4; ++q) {
        float4 v;
        v.x = s[4 * q] * inv; v.y = s[4 * q + 1] * inv;
        v.z = s[4 * q + 2] * inv; v.w = s[4 * q + 3] * inv;
        *(float4*)&Sb[sn * S_STR + sg * 16 + 4 * q] = v;
      }
    }
    __syncthreads();
    // out = S @ V : tile 4 rows (ty) x 2 d-cols (tx, tx+16) -> QB q-slot of head h
    {
      const int ty = tid >> 4, tx = tid & 15;
      float a0[4] = {0.f, 0.f, 0.f, 0.f}, a1[4] = {0.f, 0.f, 0.f, 0.f};
#pragma unroll
      for (int k0 = 0; k0 < NT; k0 += 4) {
        float4 vb0 = *(const float4*)&KVT[(96 + h * 32 + tx) * KVT_STR + k0];
        float4 vb1 = *(const float4*)&KVT[(96 + h * 32 + tx + 16) * KVT_STR + k0];
#pragma unroll
        for (int r = 0; r < 4; ++r) {
          float4 sa = *(const float4*)&Sb[(4 * ty + r) * S_STR + k0];
          a0[r] = dot4(sa, vb0, a0[r]);
          a1[r] = dot4(sa, vb1, a1[r]);
        }
      }
#pragma unroll
      for (int r = 0; r < 4; ++r) {
        QB[(4 * ty + r) * QB_STR + h * 32 + tx]      = a0[r];
        QB[(4 * ty + r) * QB_STR + h * 32 + tx + 16] = a1[r];
      }
    }
    __syncthreads();
  }

  // proj: QB(attn) -> XA ; ln2 ; fc1+gelu -> Hid ; fc2 -> QB
  gemm<96, 96, 0>(QB, QB_STR, 0, XA, XA_STR, 0, proj_w, proj_b, Ws, tid);
  ln_rows(XA, XA_STR, n2g, n2b, tid);
  __syncthreads();
  gemm<192, 96, 1>(XA, XA_STR, 0, Hid, H_STR, 0, fc1_w, fc1_b, Ws, tid);
  gemm<96, 192, 0>(Hid, H_STR, 0, QB, QB_STR, 0, fc2_w, fc2_b, Ws, tid);

  // residual + window merge
  float* ob = out + ((size_t)b * CDIM) * 65536 + (size_t)(wh * 8) * 256 + ww * 8;
  for (int i = tid; i < CDIM * NT; i += THREADS) {
    int c = i >> 6, n = i & 63;
    size_t go = (size_t)c * 65536 + (n >> 3) * 256 + (n & 7);
    ob[go] = QB[n * QB_STR + c] + xw[go];
  }
}

extern "C" void kernel_launch(void* const* d_in, const int* in_sizes, int n_in,
                              void* d_out, int out_size) {
  (void)in_sizes; (void)n_in; (void)out_size;
  cudaFuncSetAttribute(swin_kernel, cudaFuncAttributeMaxDynamicSharedMemorySize,
                       SMEM_FLOATS * (int)sizeof(float));
  swin_kernel<<<8192, THREADS, SMEM_FLOATS * sizeof(float)>>>(
      (const float*)d_in[0],
      (const float*)d_in[1], (const float*)d_in[2],
      (const float*)d_in[3], (const float*)d_in[4],
      (const float*)d_in[5],
      (const float*)d_in[6], (const float*)d_in[7],
      (const float*)d_in[8], (const float*)d_in[9],
      (const float*)d_in[10], (const float*)d_in[11],
      (const float*)d_in[12], (const float*)d_in[13],
      (float*)d_out);
}

// round 6
// speedup vs baseline: 4.0431x; 2.8044x over previous
#include <cuda_runtime.h>
#include <cuda_fp16.h>
#include <cstdint>
#include <math.h>

#define THREADS 256
constexpr float LN_EPS = 1e-5f, SCALE = 0.17677669529663687f;

constexpr int AST = 208;   // f16 tile row stride bytes (104 halves)
constexpr int VST = 272;   // VT row stride bytes (136 halves)
constexpr int HST = 400;   // hid/fc2-W row stride bytes (200 halves)
constexpr int SSTR = 98;   // fp32 scratch stride (floats)

constexpr int OF_RPB = 0, OF_BIAS = 2704, OF_LNP = 5392, OF_RIDX = 6928;
constexpr int OF_A  = 11024;   // 128x104 f16: LN1-x -> attn-out
constexpr int OF_Q  = 37648;   // q -> ln2-out
constexpr int OF_K  = 64272;   // k
constexpr int OF_VT = 90896;   // 96x136 f16 v-transposed
constexpr int OF_W  = 117008;  // weight tile (max 96x200 f16)
constexpr int OF_SCR = 155408; // fp32 scratch 128x98 ; later hid tile 128x200 f16
constexpr int OF_SCR2 = OF_A;  // fc2-out fp32 (overlays dead A+Q)
constexpr int SMEM_TOTAL = 206608;

__device__ __forceinline__ uint32_t smem_u32(const void* p) {
  uint32_t a; asm("{ .reg .u64 t; cvta.to.shared.u64 t, %1; cvt.u32.u64 %0, t; }" : "=r"(a) : "l"(p)); return a;
}
__device__ __forceinline__ uint32_t pkh(float lo, float hi) {
  __half2 h = __floats2half2_rn(lo, hi);
  return *reinterpret_cast<uint32_t*>(&h);
}
__device__ __forceinline__ void ldm4(uint32_t* r, uint32_t a) {
  asm volatile("ldmatrix.sync.aligned.m8n8.x4.shared.b16 {%0,%1,%2,%3}, [%4];"
               : "=r"(r[0]), "=r"(r[1]), "=r"(r[2]), "=r"(r[3]) : "r"(a));
}
__device__ __forceinline__ void ldm2(uint32_t* r, uint32_t a) {
  asm volatile("ldmatrix.sync.aligned.m8n8.x2.shared.b16 {%0,%1}, [%2];"
               : "=r"(r[0]), "=r"(r[1]) : "r"(a));
}
__device__ __forceinline__ void mma16816(float* d, const uint32_t* a, const uint32_t* b) {
  asm volatile(
      "mma.sync.aligned.m16n8k16.row.col.f32.f16.f16.f32 "
      "{%0,%1,%2,%3}, {%4,%5,%6,%7}, {%8,%9}, {%0,%1,%2,%3};"
      : "+f"(d[0]), "+f"(d[1]), "+f"(d[2]), "+f"(d[3])
      : "r"(a[0]), "r"(a[1]), "r"(a[2]), "r"(a[3]), "r"(b[0]), "r"(b[1]));
}

// C[16 rows x NT*8 cols] = A[16 x 16*KS] @ W[NT*8 x 16*KS]^T, per warp.
template <int NT, int KS>
__device__ __forceinline__ void wgemm(uint32_t aB, int aStr, uint32_t wB, int wStr,
                                      int m0, int lane, float (*d)[4]) {
#pragma unroll
  for (int j = 0; j < NT; ++j) { d[j][0] = d[j][1] = d[j][2] = d[j][3] = 0.f; }
  const uint32_t aRow = aB + (uint32_t)((m0 + (lane & 7) + ((lane >> 3) & 1) * 8) * aStr + (lane >> 4) * 16);
  const uint32_t wRow = wB + (uint32_t)((lane & 7) * wStr + ((lane >> 3) & 1) * 16);
#pragma unroll
  for (int s = 0; s < KS; ++s) {
    uint32_t a[4];
    ldm4(a, aRow + 32 * s);
#pragma unroll
    for (int j = 0; j < NT; ++j) {
      uint32_t b[2];
      ldm2(b, wRow + (uint32_t)(8 * j * wStr) + 32 * s);
      mma16816(d[j], a, b);
    }
  }
}

// stage fp32 row-major W[ROWS][K] -> f16 tile (row stride WSTR bytes)
template <int ROWS, int K, int WSTR>
__device__ __forceinline__ void load_w(char* SM, const float* __restrict__ w) {
  for (int p = threadIdx.x; p < ROWS * K / 2; p += THREADS) {
    int row = (2 * p) / K, col = (2 * p) % K;
    float2 v = *(const float2*)&w[row * K + col];
    *(uint32_t*)(SM + OF_W + row * WSTR + col * 2) = pkh(v.x, v.y);
  }
}

__global__ void __launch_bounds__(THREADS, 1)
swin_kernel(const float* __restrict__ x,
            const float* __restrict__ qkv_w, const float* __restrict__ qkv_b,
            const float* __restrict__ proj_w, const float* __restrict__ proj_b,
            const float* __restrict__ rpb,
            const float* __restrict__ n1g, const float* __restrict__ n1b,
            const float* __restrict__ n2g, const float* __restrict__ n2b,
            const float* __restrict__ fc1_w, const float* __restrict__ fc1_b,
            const float* __restrict__ fc2_w, const float* __restrict__ fc2_b,
            float* __restrict__ out) {
  extern __shared__ char SM[];
  const uint32_t sb = smem_u32(SM);
  const int tid = threadIdx.x, lane = tid & 31, warp = tid >> 5;
  const int m0 = warp * 16, qr = lane >> 2, qc = lane & 3;

  float* rpbs = (float*)(SM + OF_RPB);
  float* bias = (float*)(SM + OF_BIAS);
  float* lnp  = (float*)(SM + OF_LNP);
  uint8_t* RIDX = (uint8_t*)(SM + OF_RIDX);
  for (int i = tid; i < 675; i += THREADS) rpbs[i] = rpb[i];
  for (int i = tid; i < 288; i += THREADS) bias[i] = qkv_b[i];
  for (int i = tid; i < 96; i += THREADS)  bias[288 + i] = proj_b[i];
  for (int i = tid; i < 192; i += THREADS) bias[384 + i] = fc1_b[i];
  for (int i = tid; i < 96; i += THREADS)  bias[576 + i] = fc2_b[i];
  for (int i = tid; i < 96; i += THREADS) {
    lnp[i] = n1g[i]; lnp[96 + i] = n1b[i]; lnp[192 + i] = n2g[i]; lnp[288 + i] = n2b[i];
  }
  for (int i = tid; i < 4096; i += THREADS) {
    int n = i >> 6, m = i & 63;
    RIDX[i] = (uint8_t)(((n >> 3) - (m >> 3) + 7) * 15 + ((n & 7) - (m & 7) + 7));
  }

  const int w0 = 2 * blockIdx.x;
  const int wb = w0 >> 10, wh = (w0 >> 5) & 31, ww = w0 & 31;
  const int tt = tid & 63, wix = tid >> 6;  // row decomposition (tid<128)
  const float* xp = x + ((size_t)wb * 96) * 65536 +
                    (size_t)(wh * 8 + (tt >> 3)) * 256 + (ww + wix) * 8 + (tt & 7);

  // ---- LN1 -> A tile (f16) ----
  if (tid < 128) {
    float v[96], s = 0.f, s2 = 0.f;
#pragma unroll
    for (int c = 0; c < 96; ++c) { float u = xp[(size_t)c * 65536]; v[c] = u; s += u; s2 += u * u; }
    float mu = s * (1.f / 96.f);
    float rs = rsqrtf(s2 * (1.f / 96.f) - mu * mu + LN_EPS);
#pragma unroll
    for (int c = 0; c < 48; ++c) {
      float a = (v[2 * c] - mu) * rs * lnp[2 * c] + lnp[96 + 2 * c];
      float b = (v[2 * c + 1] - mu) * rs * lnp[2 * c + 1] + lnp[96 + 2 * c + 1];
      *(uint32_t*)(SM + OF_A + tid * AST + 4 * c) = pkh(a, b);
    }
  }
  __syncthreads();

  // ---- QKV: 3 chunks of N=96 ----
  for (int c = 0; c < 3; ++c) {
    load_w<96, 96, AST>(SM, qkv_w + c * 9216);
    __syncthreads();
    float d[12][4];
    wgemm<12, 6>(sb + OF_A, AST, sb + OF_W, AST, m0, lane, d);
    if (c < 2) {
      const int dst = c == 0 ? OF_Q : OF_K;
      const float sc = c == 0 ? SCALE : 1.f;
#pragma unroll
      for (int j = 0; j < 12; ++j) {
        int col = 8 * j + 2 * qc;
        float b0 = bias[96 * c + col], b1 = bias[96 * c + col + 1];
        *(uint32_t*)(SM + dst + (m0 + qr) * AST + col * 2)     = pkh((d[j][0] + b0) * sc, (d[j][1] + b1) * sc);
        *(uint32_t*)(SM + dst + (m0 + qr + 8) * AST + col * 2) = pkh((d[j][2] + b0) * sc, (d[j][3] + b1) * sc);
      }
    } else {
#pragma unroll
      for (int j = 0; j < 12; ++j) {
        int col = 8 * j + 2 * qc;
        float b0 = bias[192 + col], b1 = bias[192 + col + 1];
        *(__half*)(SM + OF_VT + col * VST + (m0 + qr) * 2)           = __float2half_rn(d[j][0] + b0);
        *(__half*)(SM + OF_VT + (col + 1) * VST + (m0 + qr) * 2)     = __float2half_rn(d[j][1] + b1);
        *(__half*)(SM + OF_VT + col * VST + (m0 + qr + 8) * 2)       = __float2half_rn(d[j][2] + b0);
        *(__half*)(SM + OF_VT + (col + 1) * VST + (m0 + qr + 8) * 2) = __float2half_rn(d[j][3] + b1);
      }
    }
    __syncthreads();
  }

  // ---- attention (fragments end-to-end) ----
  const int wb64 = (warp >> 2) * 64;
  const int nn0 = (m0 & 63) + qr, nn1 = nn0 + 8;
#pragma unroll
  for (int h = 0; h < 3; ++h) {
    float ds[8][4];
#pragma unroll
    for (int j = 0; j < 8; ++j) { ds[j][0] = ds[j][1] = ds[j][2] = ds[j][3] = 0.f; }
#pragma unroll
    for (int s = 0; s < 2; ++s) {
      uint32_t a[4];
      ldm4(a, sb + OF_Q + (uint32_t)((m0 + (lane & 7) + ((lane >> 3) & 1) * 8) * AST + (h * 32 + s * 16 + (lane >> 4) * 8) * 2));
#pragma unroll
      for (int j = 0; j < 8; ++j) {
        uint32_t b[2];
        ldm2(b, sb + OF_K + (uint32_t)((wb64 + 8 * j + (lane & 7)) * AST + (h * 32 + s * 16 + ((lane >> 3) & 1) * 8) * 2));
        mma16816(ds[j], a, b);
      }
    }
    float mx0 = -1e30f, mx1 = -1e30f;
#pragma unroll
    for (int j = 0; j < 8; ++j) {
      int mmc = 8 * j + 2 * qc;
      ds[j][0] += rpbs[RIDX[nn0 * 64 + mmc] * 3 + h];
      ds[j][1] += rpbs[RIDX[nn0 * 64 + mmc + 1] * 3 + h];
      ds[j][2] += rpbs[RIDX[nn1 * 64 + mmc] * 3 + h];
      ds[j][3] += rpbs[RIDX[nn1 * 64 + mmc + 1] * 3 + h];
      mx0 = fmaxf(mx0, fmaxf(ds[j][0], ds[j][1]));
      mx1 = fmaxf(mx1, fmaxf(ds[j][2], ds[j][3]));
    }
    mx0 = fmaxf(mx0, __shfl_xor_sync(0xffffffffu, mx0, 1));
    mx0 = fmaxf(mx0, __shfl_xor_sync(0xffffffffu, mx0, 2));
    mx1 = fmaxf(mx1, __shfl_xor_sync(0xffffffffu, mx1, 1));
    mx1 = fmaxf(mx1, __shfl_xor_sync(0xffffffffu, mx1, 2));
    float s0 = 0.f, s1 = 0.f;
#pragma unroll
    for (int j = 0; j < 8; ++j) {
      ds[j][0] = __expf(ds[j][0] - mx0); ds[j][1] = __expf(ds[j][1] - mx0);
      ds[j][2] = __expf(ds[j][2] - mx1); ds[j][3] = __expf(ds[j][3] - mx1);
      s0 += ds[j][0] + ds[j][1]; s1 += ds[j][2] + ds[j][3];
    }
    s0 += __shfl_xor_sync(0xffffffffu, s0, 1); s0 += __shfl_xor_sync(0xffffffffu, s0, 2);
    s1 += __shfl_xor_sync(0xffffffffu, s1, 1); s1 += __shfl_xor_sync(0xffffffffu, s1, 2);
    float i0 = 1.f / s0, i1 = 1.f / s1;
    uint32_t pa[4][4];
#pragma unroll
    for (int kk = 0; kk < 4; ++kk) {
      pa[kk][0] = pkh(ds[2 * kk][0] * i0, ds[2 * kk][1] * i0);
      pa[kk][1] = pkh(ds[2 * kk][2] * i1, ds[2 * kk][3] * i1);
      pa[kk][2] = pkh(ds[2 * kk + 1][0] * i0, ds[2 * kk + 1][1] * i0);
      pa[kk][3] = pkh(ds[2 * kk + 1][2] * i1, ds[2 * kk + 1][3] * i1);
    }
    float o[4][4];
#pragma unroll
    for (int j = 0; j < 4; ++j) { o[j][0] = o[j][1] = o[j][2] = o[j][3] = 0.f; }
#pragma unroll
    for (int kk = 0; kk < 4; ++kk)
#pragma unroll
      for (int j = 0; j < 4; ++j) {
        uint32_t b[2];
        ldm2(b, sb + OF_VT + (uint32_t)((h * 32 + 8 * j + (lane & 7)) * VST + (wb64 + 16 * kk + ((lane >> 3) & 1) * 8) * 2));
        mma16816(o[j], pa[kk], b);
      }
#pragma unroll
    for (int j = 0; j < 4; ++j) {
      int col = h * 32 + 8 * j + 2 * qc;
      *(uint32_t*)(SM + OF_A + (m0 + qr) * AST + col * 2)     = pkh(o[j][0], o[j][1]);
      *(uint32_t*)(SM + OF_A + (m0 + qr + 8) * AST + col * 2) = pkh(o[j][2], o[j][3]);
    }
  }
  __syncthreads();

  // ---- proj -> fp32 scratch ----
  load_w<96, 96, AST>(SM, proj_w);
  __syncthreads();
  {
    float d[12][4];
    wgemm<12, 6>(sb + OF_A, AST, sb + OF_W, AST, m0, lane, d);
    float* SC = (float*)(SM + OF_SCR);
#pragma unroll
    for (int j = 0; j < 12; ++j) {
      int col = 8 * j + 2 * qc;
      float b0 = bias[288 + col], b1 = bias[288 + col + 1];
      SC[(m0 + qr) * SSTR + col] = d[j][0] + b0;
      SC[(m0 + qr) * SSTR + col + 1] = d[j][1] + b1;
      SC[(m0 + qr + 8) * SSTR + col] = d[j][2] + b0;
      SC[(m0 + qr + 8) * SSTR + col + 1] = d[j][3] + b1;
    }
  }
  __syncthreads();

  // ---- LN2 -> Q tile (f16) ----
  if (tid < 128) {
    const float* SC = (const float*)(SM + OF_SCR);
    float s = 0.f, s2 = 0.f;
#pragma unroll
    for (int c = 0; c < 96; ++c) { float u = SC[tid * SSTR + c]; s += u; s2 += u * u; }
    float mu = s * (1.f / 96.f);
    float rs = rsqrtf(s2 * (1.f / 96.f) - mu * mu + LN_EPS);
#pragma unroll
    for (int c = 0; c < 48; ++c) {
      float a = (SC[tid * SSTR + 2 * c] - mu) * rs * lnp[192 + 2 * c] + lnp[288 + 2 * c];
      float b = (SC[tid * SSTR + 2 * c + 1] - mu) * rs * lnp[192 + 2 * c + 1] + lnp[288 + 2 * c + 1];
      *(uint32_t*)(SM + OF_Q + tid * AST + 4 * c) = pkh(a, b);
    }
  }
  __syncthreads();

  // ---- fc1 (+exact GELU) -> hid tile f16 (overlays scratch) ----
  for (int c = 0; c < 2; ++c) {
    load_w<96, 96, AST>(SM, fc1_w + c * 9216);
    __syncthreads();
    float d[12][4];
    wgemm<12, 6>(sb + OF_Q, AST, sb + OF_W, AST, m0, lane, d);
#pragma unroll
    for (int j = 0; j < 12; ++j) {
      int col = 96 * c + 8 * j + 2 * qc;
      float b0 = bias[384 + col], b1 = bias[384 + col + 1];
      float u0 = d[j][0] + b0, u1 = d[j][1] + b1, u2 = d[j][2] + b0, u3 = d[j][3] + b1;
      u0 = 0.5f * u0 * (1.f + erff(u0 * 0.70710678118654752f));
      u1 = 0.5f * u1 * (1.f + erff(u1 * 0.70710678118654752f));
      u2 = 0.5f * u2 * (1.f + erff(u2 * 0.70710678118654752f));
      u3 = 0.5f * u3 * (1.f + erff(u3 * 0.70710678118654752f));
      *(uint32_t*)(SM + OF_SCR + (m0 + qr) * HST + col * 2)     = pkh(u0, u1);
      *(uint32_t*)(SM + OF_SCR + (m0 + qr + 8) * HST + col * 2) = pkh(u2, u3);
    }
    __syncthreads();
  }

  // ---- fc2 -> fp32 (overlays dead A+Q) ----
  load_w<96, 192, HST>(SM, fc2_w);
  __syncthreads();
  {
    float d[12][4];
    wgemm<12, 12>(sb + OF_SCR, HST, sb + OF_W, HST, m0, lane, d);
    float* SC2 = (float*)(SM + OF_SCR2);
#pragma unroll
    for (int j = 0; j < 12; ++j) {
      int col = 8 * j + 2 * qc;
      float b0 = bias[576 + col], b1 = bias[576 + col + 1];
      SC2[(m0 + qr) * SSTR + col] = d[j][0] + b0;
      SC2[(m0 + qr) * SSTR + col + 1] = d[j][1] + b1;
      SC2[(m0 + qr + 8) * SSTR + col] = d[j][2] + b0;
      SC2[(m0 + qr + 8) * SSTR + col + 1] = d[j][3] + b1;
    }
  }
  __syncthreads();

  // ---- residual + window merge ----
  if (tid < 128) {
    const float* SC2 = (const float*)(SM + OF_SCR2);
    float* op = out + ((size_t)wb * 96) * 65536 +
                (size_t)(wh * 8 + (tt >> 3)) * 256 + (ww + wix) * 8 + (tt & 7);
#pragma unroll
    for (int c = 0; c < 96; ++c)
      op[(size_t)c * 65536] = SC2[tid * SSTR + c] + xp[(size_t)c * 65536];
  }
}

extern "C" void kernel_launch(void* const* d_in, const int* in_sizes, int n_in,
                              void* d_out, int out_size) {
  (void)in_sizes; (void)n_in; (void)out_size;
  cudaFuncSetAttribute(swin_kernel, cudaFuncAttributeMaxDynamicSharedMemorySize, SMEM_TOTAL);
  swin_kernel<<<4096, THREADS, SMEM_TOTAL>>>(
      (const float*)d_in[0],
      (const float*)d_in[1], (const float*)d_in[2],
      (const float*)d_in[3], (const float*)d_in[4],
      (const float*)d_in[5],
      (const float*)d_in[6], (const float*)d_in[7],
      (const float*)d_in[8], (const float*)d_in[9],
      (const float*)d_in[10], (const float*)d_in[11],
      (const float*)d_in[12], (const float*)d_in[13],
      (float*)d_out);
}